// round 3
// baseline (speedup 1.0000x reference)
#include <cuda_runtime.h>
#include <cuda_bf16.h>

#define BATCH 16384
#define FEAT 512
#define NCLS 100000
#define ALPHA 0.5f
#define LAMDA 0.003f

// Scratch: per-class sample counts (allocation-free __device__ global).
__device__ int g_counts[NCLS];

__global__ void zero_counts_kernel() {
    int i = blockIdx.x * blockDim.x + threadIdx.x;
    if (i < NCLS) g_counts[i] = 0;
}

__global__ void count_kernel(const int* __restrict__ targets) {
    int i = blockIdx.x * blockDim.x + threadIdx.x;
    if (i < BATCH) atomicAdd(&g_counts[targets[i]], 1);
}

// Vectorized copy: centers -> new_centers region of d_out.
// NCLS*FEAT/4 = 12,800,000 float4 elements.
__global__ void copy_centers_kernel(const float4* __restrict__ src,
                                    float4* __restrict__ dst) {
    int i = blockIdx.x * blockDim.x + threadIdx.x;
    if (i < (NCLS * FEAT / 4)) dst[i] = src[i];
}

// One block per batch row. 128 threads x float4 = 512 feats.
// Computes loss, target_weights, and atomically applies the center delta.
__global__ __launch_bounds__(128) void fused_main_kernel(
    const float4* __restrict__ inputs,
    const float4* __restrict__ centers,
    const float*  __restrict__ wpc,
    const int*    __restrict__ targets,
    float4* __restrict__ loss_out,
    float4* __restrict__ tw_out,
    float*  __restrict__ new_centers) {

    const int b  = blockIdx.x;
    const int d4 = threadIdx.x;               // 0..127

    const int t = __ldg(&targets[b]);
    const float w = LAMDA * __ldg(&wpc[t]);
    const float s = ALPHA / (1.0f + (float)g_counts[t]);

    const int ib = b * (FEAT / 4) + d4;
    const float4 x = inputs[ib];
    const float4 c = centers[(size_t)t * (FEAT / 4) + d4];

    float4 l;
    float dx;
    dx = x.x - c.x; l.x = 0.5f * dx * dx;
    dx = x.y - c.y; l.y = 0.5f * dx * dx;
    dx = x.z - c.z; l.z = 0.5f * dx * dx;
    dx = x.w - c.w; l.w = 0.5f * dx * dx;

    loss_out[ib] = l;
    tw_out[ib]   = make_float4(w, w, w, w);

    // Scatter-subtract ALPHA * x / (1 + count) into new_centers[t].
    // Duplicated classes are rare (~1.3k pairs over 16384 samples / 100k
    // classes), so these are near-conflict-free RED.F32 ops.
    float* dst = new_centers + (size_t)t * FEAT + d4 * 4;
    atomicAdd(dst + 0, -s * x.x);
    atomicAdd(dst + 1, -s * x.y);
    atomicAdd(dst + 2, -s * x.z);
    atomicAdd(dst + 3, -s * x.w);
}

extern "C" void kernel_launch(void* const* d_in, const int* in_sizes, int n_in,
                              void* d_out, int out_size) {
    const float* inputs  = (const float*)d_in[0];   // [BATCH, FEAT]
    const float* centers = (const float*)d_in[1];   // [NCLS, FEAT]
    const float* wpc     = (const float*)d_in[2];   // [NCLS]
    const int*   targets = (const int*)d_in[3];     // [BATCH]

    float* out  = (float*)d_out;
    float* loss = out;                                  // [BATCH, FEAT]
    float* tw   = out + (size_t)BATCH * FEAT;           // [BATCH, FEAT]
    float* newc = out + (size_t)2 * BATCH * FEAT;       // [NCLS, FEAT]

    zero_counts_kernel<<<(NCLS + 255) / 256, 256>>>();
    count_kernel<<<(BATCH + 255) / 256, 256>>>(targets);
    copy_centers_kernel<<<(NCLS * FEAT / 4 + 255) / 256, 256>>>(
        (const float4*)centers, (float4*)newc);
    fused_main_kernel<<<BATCH, 128>>>(
        (const float4*)inputs, (const float4*)centers, wpc, targets,
        (float4*)loss, (float4*)tw, newc);
}